// round 2
// baseline (speedup 1.0000x reference)
#include <cuda_runtime.h>

// global accumulators (zero-initialized at load; reset by last block each run)
__device__ double g_rot_acc[64];
__device__ double g_str_acc[64];
__device__ unsigned int g_ticket = 0;

#define TPB 256

__global__ void __launch_bounds__(TPB)
chain_kernel(const float2* __restrict__ pos,
             const float*  __restrict__ th_ss,
             const float*  __restrict__ rest,
             const float*  __restrict__ p_kstiff,
             const float*  __restrict__ p_ksoft,
             const float*  __restrict__ p_kstretch,
             const int2*   __restrict__ buckle,
             float*        __restrict__ out,
             int H, int nblocks)
{
    const int N   = H + 2;
    const int P0  = blockIdx.x * TPB;
    const int tid = threadIdx.x;

    // positions j in [0,260) map to pos[P0-2+j]
    __shared__ float2 spos[TPB + 4];
    // hinge i in [0,258) maps to hinge h = P0-2+i
    __shared__ float2 s_ga[TPB + 2];   // contribution to point a (=h)
    __shared__ float2 s_gb[TPB + 2];   // contribution to point b (=h+1)
    __shared__ float2 s_gc[TPB + 2];   // contribution to point c (=h+2)
    __shared__ float  s_e [TPB + 2];   // hinge rotational energy

    const float k_stiff   = __ldg(p_kstiff);
    const float k_soft    = __ldg(p_ksoft);
    const float k_stretch = __ldg(p_kstretch);

    // ---- stage positions ----
    #pragma unroll
    for (int j = tid; j < TPB + 4; j += TPB) {
        int g = P0 - 2 + j;
        g = max(0, min(g, N - 1));
        spos[j] = __ldg(&pos[g]);
    }
    __syncthreads();

    // ---- stage hinge contributions (each hinge computed once) ----
    #pragma unroll
    for (int i = tid; i < TPB + 2; i += TPB) {
        int h = P0 - 2 + i;
        float2 ga = make_float2(0.f, 0.f);
        float2 gb = make_float2(0.f, 0.f);
        float2 gc = make_float2(0.f, 0.f);
        float  e  = 0.f;
        if (h >= 0 && h < H) {
            float2 A = spos[i], Bp = spos[i + 1], C = spos[i + 2];
            float v1x = Bp.x - A.x,  v1y = Bp.y - A.y;
            float v2x = C.x  - Bp.x, v2y = C.y  - Bp.y;
            float cr = v1x * v2y - v1y * v2x;
            float dt = v1x * v2x + v1y * v2y;
            float theta = atan2f(cr, dt);   // keep libm: mask-threshold bit-safety vs ref

            float th = __ldg(&th_ss[h]);
            int2  B  = __ldg(&buckle[h]);
            bool m0 = (B.x == 1 && theta > -th) || (B.x == -1 && theta < th);
            bool m1 = (B.y == 1 && theta > -th) || (B.y == -1 && theta < th);
            float keff = (m0 ? k_stiff : k_soft) + (m1 ? k_stiff : k_soft);

            float diff = theta - th;
            float g = keff * diff;
            e = 0.5f * g * diff;

            // fold g into the 1/r^2 factor
            float inv = __fdividef(g, fmaf(cr, cr, dt * dt));
            float d1x = ( dt * v2y - cr * v2x) * inv;
            float d1y = (-dt * v2x - cr * v2y) * inv;
            float d2x = (-dt * v1y - cr * v1x) * inv;
            float d2y = ( dt * v1x - cr * v1y) * inv;

            ga = make_float2(-d1x,       -d1y);
            gb = make_float2(d1x - d2x,  d1y - d2y);
            gc = make_float2(d2x,        d2y);
        }
        s_ga[i] = ga; s_gb[i] = gb; s_gc[i] = gc; s_e[i] = e;
    }
    __syncthreads();

    // ---- per-point gather + stretch + force write ----
    const int p = P0 + tid;
    float rot_e = 0.f, str_e = 0.f;
    if (p < N) {
        float gx = s_ga[tid + 2].x + s_gb[tid + 1].x + s_gc[tid].x;
        float gy = s_ga[tid + 2].y + s_gb[tid + 1].y + s_gc[tid].y;
        rot_e = s_e[tid + 2];   // zero if hinge p invalid

        float2 Pm1 = spos[tid + 1], Pc = spos[tid + 2], Pp1 = spos[tid + 3];

        if (p <= H) {  // edge p (this thread owns its energy)
            float ex = Pp1.x - Pc.x, ey = Pp1.y - Pc.y;
            float len = sqrtf(fmaf(ex, ex, ey * ey));
            float dl  = len - __ldg(&rest[p]);
            str_e = 0.5f * k_stretch * dl * dl;
            float c = k_stretch * dl * __fdividef(1.0f, len);
            gx -= c * ex; gy -= c * ey;
        }
        if (p >= 1) {  // edge p-1 (always valid for p>=1)
            float ex = Pc.x - Pm1.x, ey = Pc.y - Pm1.y;
            float len = sqrtf(fmaf(ex, ex, ey * ey));
            float dl  = len - __ldg(&rest[p - 1]);
            float c = k_stretch * dl * __fdividef(1.0f, len);
            gx += c * ex; gy += c * ey;
        }

        out[3 + 2 * p]     = (p < 2) ? 0.f : -gx;
        out[3 + 2 * p + 1] = (p < 2) ? 0.f : -gy;
    }

    // ---- energy reduction (double) ----
    double r = (double)rot_e;
    double s = (double)str_e;
    #pragma unroll
    for (int off = 16; off > 0; off >>= 1) {
        r += __shfl_down_sync(0xffffffffu, r, off);
        s += __shfl_down_sync(0xffffffffu, s, off);
    }
    __shared__ double sr[TPB / 32];
    __shared__ double ss[TPB / 32];
    const int wid  = tid >> 5;
    const int lane = tid & 31;
    if (lane == 0) { sr[wid] = r; ss[wid] = s; }
    __syncthreads();

    if (tid == 0) {
        double rt = 0.0, st = 0.0;
        #pragma unroll
        for (int i = 0; i < TPB / 32; i++) { rt += sr[i]; st += ss[i]; }
        int slot = blockIdx.x & 63;
        atomicAdd(&g_rot_acc[slot], rt);
        atomicAdd(&g_str_acc[slot], st);
        __threadfence();
        unsigned t = atomicAdd(&g_ticket, 1u);
        if (t == (unsigned)(nblocks - 1)) {
            // last block: finalize and reset state for next (graph-replayed) run
            double R = 0.0, S = 0.0;
            #pragma unroll
            for (int i = 0; i < 64; i++) {
                R += g_rot_acc[i]; g_rot_acc[i] = 0.0;
                S += g_str_acc[i]; g_str_acc[i] = 0.0;
            }
            out[0] = (float)(R + S);
            out[1] = (float)R;
            out[2] = (float)S;
            g_ticket = 0u;
        }
    }
}

extern "C" void kernel_launch(void* const* d_in, const int* in_sizes, int n_in,
                              void* d_out, int out_size) {
    const float2* pos      = (const float2*)d_in[0];
    const float*  th_ss    = (const float*)d_in[1];
    const float*  rest     = (const float*)d_in[2];
    const float*  kstiff   = (const float*)d_in[3];
    const float*  ksoft    = (const float*)d_in[4];
    const float*  kstretch = (const float*)d_in[5];
    const int2*   buckle   = (const int2*)d_in[6];
    float* out = (float*)d_out;

    const int H = in_sizes[1];      // thetas_ss element count
    const int N = H + 2;
    const int blocks = (N + TPB - 1) / TPB;

    chain_kernel<<<blocks, TPB>>>(pos, th_ss, rest, kstiff, ksoft, kstretch,
                                  buckle, out, H, blocks);
}

// round 3
// speedup vs baseline: 2.2713x; 2.2713x over previous
#include <cuda_runtime.h>

__device__ double g_rot_acc[64];
__device__ double g_str_acc[64];
__device__ unsigned int g_ticket = 0;

#define TPB 256
#define PPT 4

// Branch-free atan2, cephes 4-term core on |z|<=tan(pi/8). Abs err ~1e-7 rad.
__device__ __forceinline__ float fast_atan2f(float y, float x) {
    float ay = fabsf(y), ax = fabsf(x);
    float mn = fminf(ay, ax), mx = fmaxf(ay, ax);
    bool  big = mn > 0.41421356237f * mx;
    float num = big ? (mn - mx) : mn;
    float den = big ? (mn + mx) : mx;
    float z = __fdividef(num, den);
    float s = z * z;
    float p = fmaf(fmaf(fmaf(fmaf(8.05374449538e-2f, s, -1.38776856032e-1f), s,
                             1.99777106478e-1f), s, -3.33329491539e-1f),
                   s * z, z);
    float r = big ? (0.78539816339744831f + p) : p;
    if (ay > ax) r = 1.57079632679489662f - r;
    if (x < 0.0f) r = 3.14159265358979323f - r;
    return copysignf(r, y);
}

struct HC { float gax, gay, gbx, gby, gcx, gcy, e; };

__device__ __forceinline__ HC hinge_calc(float2 A, float2 Bp, float2 C,
                                         float th, int2 B,
                                         float k_stiff, float k_soft)
{
    float v1x = Bp.x - A.x,  v1y = Bp.y - A.y;
    float v2x = C.x  - Bp.x, v2y = C.y  - Bp.y;
    float cr = v1x * v2y - v1y * v2x;
    float dt = fmaf(v1x, v2x, v1y * v2y);
    float theta = fast_atan2f(cr, dt);

    bool m0 = (B.x == 1 && theta > -th) || (B.x == -1 && theta < th);
    bool m1 = (B.y == 1 && theta > -th) || (B.y == -1 && theta < th);
    float keff = (m0 ? k_stiff : k_soft) + (m1 ? k_stiff : k_soft);

    float diff = theta - th;
    float g = keff * diff;

    float inv = __fdividef(g, fmaf(cr, cr, dt * dt));
    float d1x = ( dt * v2y - cr * v2x) * inv;
    float d1y = (-dt * v2x - cr * v2y) * inv;
    float d2x = (-dt * v1y - cr * v1x) * inv;
    float d2y = ( dt * v1x - cr * v1y) * inv;

    HC o;
    o.gax = -d1x;        o.gay = -d1y;
    o.gbx = d1x - d2x;   o.gby = d1y - d2y;
    o.gcx = d2x;         o.gcy = d2y;
    o.e   = 0.5f * g * diff;
    return o;
}

__global__ void __launch_bounds__(TPB)
chain_kernel(const float2* __restrict__ pos,
             const float*  __restrict__ th_ss,
             const float*  __restrict__ rest,
             const float*  __restrict__ p_kstiff,
             const float*  __restrict__ p_ksoft,
             const float*  __restrict__ p_kstretch,
             const int2*   __restrict__ buckle,
             float*        __restrict__ out,
             int H, unsigned totalWarps)
{
    const int N = H + 2;
    const int t = blockIdx.x * TPB + threadIdx.x;
    const int s = t * PPT;                   // first owned point

    const float k_stiff   = __ldg(p_kstiff);
    const float k_soft    = __ldg(p_ksoft);
    const float k_stretch = __ldg(p_kstretch);

    float2 P[PPT + 4];                        // points s-2 .. s+5
    float  TH[PPT + 2];                       // hinges s-2 .. s+3
    int2   BK[PPT + 2];
    float  RL[PPT + 1];                       // edges  s-1 .. s+3
    bool   vH[PPT + 2], vE[PPT + 1];

    float rot_e = 0.f, str_e = 0.f;

    if (s < N) {
        const bool fast = (s >= PPT) && (s + 6 <= N);
        if (fast) {
            const float4* p4 = (const float4*)(pos + (s - 2));
            #pragma unroll
            for (int i = 0; i < 4; i++) {
                float4 v = __ldg(&p4[i]);
                P[2 * i]     = make_float2(v.x, v.y);
                P[2 * i + 1] = make_float2(v.z, v.w);
            }
            const float2* t2 = (const float2*)(th_ss + (s - 2));
            #pragma unroll
            for (int i = 0; i < 3; i++) {
                float2 v = __ldg(&t2[i]);
                TH[2 * i] = v.x; TH[2 * i + 1] = v.y;
            }
            const int4* b4 = (const int4*)(buckle + (s - 2));
            #pragma unroll
            for (int i = 0; i < 3; i++) {
                int4 v = __ldg(&b4[i]);
                BK[2 * i]     = make_int2(v.x, v.y);
                BK[2 * i + 1] = make_int2(v.z, v.w);
            }
            RL[0] = __ldg(&rest[s - 1]);
            float4 r4 = __ldg((const float4*)(rest + s));
            RL[1] = r4.x; RL[2] = r4.y; RL[3] = r4.z; RL[4] = r4.w;
            #pragma unroll
            for (int i = 0; i < PPT + 2; i++) vH[i] = true;
            #pragma unroll
            for (int i = 0; i < PPT + 1; i++) vE[i] = true;
        } else {
            #pragma unroll
            for (int j = 0; j < PPT + 4; j++) {
                int g = s - 2 + j;
                g = max(0, min(g, N - 1));
                P[j] = __ldg(&pos[g]);
            }
            #pragma unroll
            for (int i = 0; i < PPT + 2; i++) {
                int h = s - 2 + i;
                vH[i] = (h >= 0) && (h < H);
                TH[i] = vH[i] ? __ldg(&th_ss[h]) : 0.f;
                BK[i] = vH[i] ? __ldg(&buckle[h]) : make_int2(0, 0);
            }
            #pragma unroll
            for (int k = 0; k < PPT + 1; k++) {
                int e = s - 1 + k;
                vE[k] = (e >= 0) && (e < N - 1);
                RL[k] = vE[k] ? __ldg(&rest[e]) : 1.f;
            }
        }

        // ---- 6 independent hinge evaluations (ILP) ----
        HC hc[PPT + 2];
        #pragma unroll
        for (int i = 0; i < PPT + 2; i++) {
            if (vH[i]) {
                hc[i] = hinge_calc(P[i], P[i + 1], P[i + 2], TH[i], BK[i],
                                   k_stiff, k_soft);
            } else {
                hc[i].gax = hc[i].gay = hc[i].gbx = hc[i].gby =
                hc[i].gcx = hc[i].gcy = hc[i].e = 0.f;
            }
        }

        // ---- 5 edges (edge k spans P[k+1] -> P[k+2]) ----
        float Fx[PPT + 1], Fy[PPT + 1], Es[PPT + 1];
        #pragma unroll
        for (int k = 0; k < PPT + 1; k++) {
            if (vE[k]) {
                float ex = P[k + 2].x - P[k + 1].x;
                float ey = P[k + 2].y - P[k + 1].y;
                float len = sqrtf(fmaf(ex, ex, ey * ey));
                float dl  = len - RL[k];
                float c   = k_stretch * dl * __fdividef(1.0f, len);
                Fx[k] = c * ex; Fy[k] = c * ey;
                Es[k] = 0.5f * k_stretch * dl * dl;
            } else {
                Fx[k] = Fy[k] = Es[k] = 0.f;
            }
        }

        // ---- owned energies: hinges s..s+3 (idx 2..5), edges s..s+3 (idx 1..4)
        #pragma unroll
        for (int j = 0; j < PPT; j++) {
            rot_e += hc[j + 2].e;
            str_e += Es[j + 1];
        }

        // ---- per-point gradient assembly + force write ----
        #pragma unroll
        for (int j = 0; j < PPT; j++) {
            int p = s + j;
            if (p < N) {
                float gx = hc[j + 2].gax + hc[j + 1].gbx + hc[j].gcx
                         - Fx[j + 1] + Fx[j];
                float gy = hc[j + 2].gay + hc[j + 1].gby + hc[j].gcy
                         - Fy[j + 1] + Fy[j];
                float fx = (p < 2) ? 0.f : -gx;
                float fy = (p < 2) ? 0.f : -gy;
                out[3 + 2 * p]     = fx;
                out[3 + 2 * p + 1] = fy;
            }
        }
    }

    // ---- warp reduction (float partials -> double atomics) ----
    float r = rot_e, sv = str_e;
    #pragma unroll
    for (int off = 16; off > 0; off >>= 1) {
        r  += __shfl_down_sync(0xffffffffu, r,  off);
        sv += __shfl_down_sync(0xffffffffu, sv, off);
    }
    const int lane = threadIdx.x & 31;
    const int wid  = threadIdx.x >> 5;
    if (lane == 0) {
        int slot = (blockIdx.x * 8 + wid) & 63;
        atomicAdd(&g_rot_acc[slot], (double)r);
        atomicAdd(&g_str_acc[slot], (double)sv);
        __threadfence();
        unsigned tk = atomicAdd(&g_ticket, 1u);
        if (tk == totalWarps - 1u) {
            double R = 0.0, S = 0.0;
            #pragma unroll
            for (int i = 0; i < 64; i++) {
                R += g_rot_acc[i]; g_rot_acc[i] = 0.0;
                S += g_str_acc[i]; g_str_acc[i] = 0.0;
            }
            out[0] = (float)(R + S);
            out[1] = (float)R;
            out[2] = (float)S;
            g_ticket = 0u;
        }
    }
}

extern "C" void kernel_launch(void* const* d_in, const int* in_sizes, int n_in,
                              void* d_out, int out_size) {
    const float2* pos      = (const float2*)d_in[0];
    const float*  th_ss    = (const float*)d_in[1];
    const float*  rest     = (const float*)d_in[2];
    const float*  kstiff   = (const float*)d_in[3];
    const float*  ksoft    = (const float*)d_in[4];
    const float*  kstretch = (const float*)d_in[5];
    const int2*   buckle   = (const int2*)d_in[6];
    float* out = (float*)d_out;

    const int H = in_sizes[1];
    const int N = H + 2;
    const int threads_needed = (N + PPT - 1) / PPT;
    const int blocks = (threads_needed + TPB - 1) / TPB;
    const unsigned totalWarps = (unsigned)blocks * (TPB / 32);

    chain_kernel<<<blocks, TPB>>>(pos, th_ss, rest, kstiff, ksoft, kstretch,
                                  buckle, out, H, totalWarps);
}

// round 4
// speedup vs baseline: 3.4976x; 1.5399x over previous
#include <cuda_runtime.h>

__device__ double g_rot_acc[64];
__device__ double g_str_acc[64];
__device__ unsigned int g_ticket = 0;

#define TPB 128
#define PPT 8
#define NH (PPT + 2)   // 10 hinges per thread: h = s-2 .. s+7
#define NE (PPT + 3)   // 11 edge vectors: edge j = s-2+j .. (j=0..10)

// Branch-free atan2 (cephes core), abs err ~1e-7 rad, 1 MUFU.RCP.
__device__ __forceinline__ float fast_atan2f(float y, float x) {
    float ay = fabsf(y), ax = fabsf(x);
    float mn = fminf(ay, ax), mx = fmaxf(ay, ax);
    bool  big = mn > 0.41421356237f * mx;
    float num = big ? (mn - mx) : mn;
    float den = big ? (mn + mx) : mx;
    float z = __fdividef(num, den);
    float s = z * z;
    float p = fmaf(fmaf(fmaf(fmaf(8.05374449538e-2f, s, -1.38776856032e-1f), s,
                             1.99777106478e-1f), s, -3.33329491539e-1f),
                   s * z, z);
    float r = big ? (0.78539816339744831f + p) : p;
    if (ay > ax) r = 1.57079632679489662f - r;
    if (x < 0.0f) r = 3.14159265358979323f - r;
    return copysignf(r, y);
}

__global__ void __launch_bounds__(TPB)
chain_kernel(const float2* __restrict__ pos,
             const float*  __restrict__ th_ss,
             const float*  __restrict__ rest,
             const float*  __restrict__ p_kstiff,
             const float*  __restrict__ p_ksoft,
             const float*  __restrict__ p_kstretch,
             const int2*   __restrict__ buckle,
             float*        __restrict__ out,
             int H, unsigned totalWarps)
{
    const int N = H + 2;
    const int t = blockIdx.x * TPB + threadIdx.x;
    const int s = t * PPT;

    const float k_stiff   = __ldg(p_kstiff);
    const float k_soft    = __ldg(p_ksoft);
    const float k_stretch = __ldg(p_kstretch);

    float rot_e = 0.f, str_e = 0.f;

    if (s < N) {
        float Ex[NE], Ey[NE];
        float TH[NH], B0[NH], B1[NH];
        float RL[NE];                 // RL[j] = rest for edge-vec j (j=1..9 used)
        bool  vH[NH], vE[NE];

        const bool fast = (s >= PPT) && (s + PPT <= H);

        if (fast) {
            // points s-2 .. s+9 : 6 aligned float4
            float px[PPT + 4], py[PPT + 4];
            const float4* p4 = (const float4*)(pos + (s - 2));
            #pragma unroll
            for (int i = 0; i < 6; i++) {
                float4 v = __ldg(&p4[i]);
                px[2 * i] = v.x; py[2 * i] = v.y;
                px[2 * i + 1] = v.z; py[2 * i + 1] = v.w;
            }
            #pragma unroll
            for (int j = 0; j < NE; j++) {
                Ex[j] = px[j + 1] - px[j];
                Ey[j] = py[j + 1] - py[j];
            }
            TH[0] = __ldg(&th_ss[s - 2]);
            TH[1] = __ldg(&th_ss[s - 1]);
            {
                float4 a = __ldg((const float4*)(th_ss + s));
                float4 b = __ldg((const float4*)(th_ss + s + 4));
                TH[2] = a.x; TH[3] = a.y; TH[4] = a.z; TH[5] = a.w;
                TH[6] = b.x; TH[7] = b.y; TH[8] = b.z; TH[9] = b.w;
            }
            const int4* b4 = (const int4*)(buckle + (s - 2));
            #pragma unroll
            for (int i = 0; i < 5; i++) {
                int4 v = __ldg(&b4[i]);
                B0[2 * i]     = (float)v.x; B1[2 * i]     = (float)v.y;
                B0[2 * i + 1] = (float)v.z; B1[2 * i + 1] = (float)v.w;
            }
            RL[0] = 1.f;
            RL[1] = __ldg(&rest[s - 1]);
            {
                float4 a = __ldg((const float4*)(rest + s));
                float4 b = __ldg((const float4*)(rest + s + 4));
                RL[2] = a.x; RL[3] = a.y; RL[4] = a.z; RL[5] = a.w;
                RL[6] = b.x; RL[7] = b.y; RL[8] = b.z; RL[9] = b.w;
            }
            RL[10] = 1.f;
            #pragma unroll
            for (int i = 0; i < NH; i++) vH[i] = true;
            #pragma unroll
            for (int j = 0; j < NE; j++) vE[j] = true;
        } else {
            float px[PPT + 4], py[PPT + 4];
            #pragma unroll
            for (int j = 0; j < PPT + 4; j++) {
                int g = max(0, min(s - 2 + j, N - 1));
                float2 v = __ldg(&pos[g]);
                px[j] = v.x; py[j] = v.y;
            }
            #pragma unroll
            for (int j = 0; j < NE; j++) {
                Ex[j] = px[j + 1] - px[j];
                Ey[j] = py[j + 1] - py[j];
            }
            #pragma unroll
            for (int i = 0; i < NH; i++) {
                int h = s - 2 + i;
                vH[i] = (h >= 0) && (h < H);
                TH[i] = vH[i] ? __ldg(&th_ss[h]) : 0.f;
                int2 b = vH[i] ? __ldg(&buckle[h]) : make_int2(0, 0);
                B0[i] = (float)b.x; B1[i] = (float)b.y;
            }
            #pragma unroll
            for (int j = 0; j < NE; j++) {
                int e = s - 2 + j;
                vE[j] = (e >= 0) && (e <= H);
                RL[j] = vE[j] ? __ldg(&rest[e]) : 1.f;
            }
        }

        // ---------------- hinges (10 independent chains) ----------------
        float Gx[PPT], Gy[PPT];
        #pragma unroll
        for (int j = 0; j < PPT; j++) { Gx[j] = 0.f; Gy[j] = 0.f; }

        #pragma unroll
        for (int i = 0; i < NH; i++) {
            float v1x = Ex[i],     v1y = Ey[i];
            float v2x = Ex[i + 1], v2y = Ey[i + 1];
            float cr = v1x * v2y - v1y * v2x;
            float dt = fmaf(v1x, v2x, v1y * v2y);
            cr = vH[i] ? cr : 0.f;           // safe atan2(0,1)=0 for invalid
            dt = vH[i] ? dt : 1.f;
            float theta = fast_atan2f(cr, dt);

            float th = TH[i];
            // stiff iff theta*b + th > 0  (b = +-1)
            bool m0 = fmaf(theta, B0[i], th) > 0.f;
            bool m1 = fmaf(theta, B1[i], th) > 0.f;
            float keff = (m0 ? k_stiff : k_soft) + (m1 ? k_stiff : k_soft);

            float diff = theta - th;          // 0 for invalid (theta=0, th=0)
            float g = keff * diff;
            if (i >= 2) rot_e = fmaf(0.5f * g, diff, rot_e);

            float inv = __fdividef(g, fmaf(cr, cr, dt * dt));
            float d1x = ( dt * v2y - cr * v2x) * inv;
            float d1y = (-dt * v2x - cr * v2y) * inv;
            float d2x = (-dt * v1y - cr * v1x) * inv;
            float d2y = ( dt * v1x - cr * v1y) * inv;

            // ga -> point (i-2), gb -> (i-1), gc -> (i)  [local owned idx]
            if (i >= 2) { Gx[i - 2] -= d1x;        Gy[i - 2] -= d1y; }
            if (i >= 1 && i - 1 < PPT) {
                Gx[i - 1] += d1x - d2x;  Gy[i - 1] += d1y - d2y;
            }
            if (i < PPT) { Gx[i] += d2x;  Gy[i] += d2y; }
        }

        // ---------------- stretch (edges j=1..9) ----------------
        float Fx[NE], Fy[NE];
        #pragma unroll
        for (int j = 1; j < NE - 1; j++) {
            float ex = Ex[j], ey = Ey[j];
            float lensq = fmaf(ex, ex, ey * ey);
            lensq = vE[j] ? lensq : 1.f;
            float rsq = rsqrtf(lensq);
            float len = lensq * rsq;         // len, 1/len from ONE MUFU
            float dl  = len - RL[j];
            dl = vE[j] ? dl : 0.f;
            float c = k_stretch * dl * rsq;
            Fx[j] = c * ex; Fy[j] = c * ey;
            if (j >= 2) str_e = fmaf(0.5f * k_stretch * dl, dl, str_e);
        }

        // grad += F(edge p-1) - F(edge p);  edge p-1 = vec j+1, edge p = vec j+2
        #pragma unroll
        for (int j = 0; j < PPT; j++) {
            if (j + 2 < NE - 1) { Gx[j] -= Fx[j + 2]; Gy[j] -= Fy[j + 2]; }
            Gx[j] += Fx[j + 1]; Gy[j] += Fy[j + 1];
        }
        // j = PPT-1 uses Fx[PPT+1] = Fx[9] ok; Fx[10] never needed (j+2=10 excluded? no:
        // j=8? PPT=8 so j max 7, j+2=9 < 10 ✓ all covered)

        // ---------------- force writes ----------------
        float f[2 * PPT];
        #pragma unroll
        for (int j = 0; j < PPT; j++) {
            int p = s + j;
            f[2 * j]     = (p < 2) ? 0.f : -Gx[j];
            f[2 * j + 1] = (p < 2) ? 0.f : -Gy[j];
        }
        if (s + PPT <= N) {
            // out indices 3+2s .. 18+2s ; element (4+2s) is 16B aligned
            out[3 + 2 * s] = f[0];
            float4* o4 = (float4*)(out + 4 + 2 * s);
            o4[0] = make_float4(f[1], f[2],  f[3],  f[4]);
            o4[1] = make_float4(f[5], f[6],  f[7],  f[8]);
            o4[2] = make_float4(f[9], f[10], f[11], f[12]);
            out[16 + 2 * s] = f[13];
            out[17 + 2 * s] = f[14];
            out[18 + 2 * s] = f[15];
        } else {
            #pragma unroll
            for (int j = 0; j < PPT; j++) {
                int p = s + j;
                if (p < N) {
                    out[3 + 2 * p]     = f[2 * j];
                    out[3 + 2 * p + 1] = f[2 * j + 1];
                }
            }
        }
    }

    // ---------------- energy reduction ----------------
    float r = rot_e, sv = str_e;
    #pragma unroll
    for (int off = 16; off > 0; off >>= 1) {
        r  += __shfl_down_sync(0xffffffffu, r,  off);
        sv += __shfl_down_sync(0xffffffffu, sv, off);
    }
    const int lane = threadIdx.x & 31;
    const int wid  = threadIdx.x >> 5;
    if (lane == 0) {
        int slot = (blockIdx.x * (TPB / 32) + wid) & 63;
        atomicAdd(&g_rot_acc[slot], (double)r);
        atomicAdd(&g_str_acc[slot], (double)sv);
        __threadfence();
        unsigned tk = atomicAdd(&g_ticket, 1u);
        if (tk == totalWarps - 1u) {
            double R = 0.0, S = 0.0;
            #pragma unroll
            for (int i = 0; i < 64; i++) {
                R += g_rot_acc[i]; g_rot_acc[i] = 0.0;
                S += g_str_acc[i]; g_str_acc[i] = 0.0;
            }
            out[0] = (float)(R + S);
            out[1] = (float)R;
            out[2] = (float)S;
            g_ticket = 0u;
        }
    }
}

extern "C" void kernel_launch(void* const* d_in, const int* in_sizes, int n_in,
                              void* d_out, int out_size) {
    const float2* pos      = (const float2*)d_in[0];
    const float*  th_ss    = (const float*)d_in[1];
    const float*  rest     = (const float*)d_in[2];
    const float*  kstiff   = (const float*)d_in[3];
    const float*  ksoft    = (const float*)d_in[4];
    const float*  kstretch = (const float*)d_in[5];
    const int2*   buckle   = (const int2*)d_in[6];
    float* out = (float*)d_out;

    const int H = in_sizes[1];
    const int N = H + 2;
    const int threads_needed = (N + PPT - 1) / PPT;
    const int blocks = (threads_needed + TPB - 1) / TPB;
    const unsigned totalWarps = (unsigned)blocks * (TPB / 32);

    chain_kernel<<<blocks, TPB>>>(pos, th_ss, rest, kstiff, ksoft, kstretch,
                                  buckle, out, H, totalWarps);
}

// round 5
// speedup vs baseline: 3.7938x; 1.0847x over previous
#include <cuda_runtime.h>

__device__ double g_rot_acc[64];
__device__ double g_str_acc[64];
__device__ unsigned int g_ticket = 0;

#define TPB 128
#define PPT 8
#define NH (PPT + 2)   // 10 hinges per thread: h = s-2 .. s+7
#define NE (PPT + 3)   // 11 edge vectors: vec j spans points (s-2+j) -> (s-1+j)

// Branch-free atan2 (cephes core), abs err ~1e-7 rad, 1 MUFU.RCP.
__device__ __forceinline__ float fast_atan2f(float y, float x) {
    float ay = fabsf(y), ax = fabsf(x);
    float mn = fminf(ay, ax), mx = fmaxf(ay, ax);
    bool  big = mn > 0.41421356237f * mx;
    float num = big ? (mn - mx) : mn;
    float den = big ? (mn + mx) : mx;
    float z = __fdividef(num, den);
    float s = z * z;
    float p = fmaf(fmaf(fmaf(fmaf(8.05374449538e-2f, s, -1.38776856032e-1f), s,
                             1.99777106478e-1f), s, -3.33329491539e-1f),
                   s * z, z);
    float r = big ? (0.78539816339744831f + p) : p;
    if (ay > ax) r = 1.57079632679489662f - r;
    if (x < 0.0f) r = 3.14159265358979323f - r;
    return copysignf(r, y);
}

__global__ void __launch_bounds__(TPB, 6)
chain_kernel(const float2* __restrict__ pos,
             const float*  __restrict__ th_ss,
             const float*  __restrict__ rest,
             const float*  __restrict__ p_kstiff,
             const float*  __restrict__ p_ksoft,
             const float*  __restrict__ p_kstretch,
             const int2*   __restrict__ buckle,
             float*        __restrict__ out,
             int H, unsigned totalWarps)
{
    const int N = H + 2;
    const int t = blockIdx.x * TPB + threadIdx.x;
    const int s = t * PPT;

    const float k_stiff   = __ldg(p_kstiff);
    const float k_soft    = __ldg(p_ksoft);
    const float k_stretch = __ldg(p_kstretch);

    float rot_e = 0.f, str_e = 0.f;

    if (s < N) {
        float Ex[NE], Ey[NE];
        float TH[NH], B0[NH], B1[NH];
        float RL[NE];
        float Gx[PPT], Gy[PPT];

        const bool fast = (s >= PPT) && (s + PPT <= H);

        if (fast) {
            {   // points s-2 .. s+9 -> edge vectors (positions die immediately)
                float px[PPT + 4], py[PPT + 4];
                const float4* p4 = (const float4*)(pos + (s - 2));
                #pragma unroll
                for (int i = 0; i < 6; i++) {
                    float4 v = __ldg(&p4[i]);
                    px[2 * i] = v.x; py[2 * i] = v.y;
                    px[2 * i + 1] = v.z; py[2 * i + 1] = v.w;
                }
                #pragma unroll
                for (int j = 0; j < NE; j++) {
                    Ex[j] = px[j + 1] - px[j];
                    Ey[j] = py[j + 1] - py[j];
                }
            }
            TH[0] = __ldg(&th_ss[s - 2]);
            TH[1] = __ldg(&th_ss[s - 1]);
            {
                float4 a = __ldg((const float4*)(th_ss + s));
                float4 b = __ldg((const float4*)(th_ss + s + 4));
                TH[2] = a.x; TH[3] = a.y; TH[4] = a.z; TH[5] = a.w;
                TH[6] = b.x; TH[7] = b.y; TH[8] = b.z; TH[9] = b.w;
            }
            const int4* b4 = (const int4*)(buckle + (s - 2));
            #pragma unroll
            for (int i = 0; i < 5; i++) {
                int4 v = __ldg(&b4[i]);
                B0[2 * i]     = (float)v.x; B1[2 * i]     = (float)v.y;
                B0[2 * i + 1] = (float)v.z; B1[2 * i + 1] = (float)v.w;
            }
            RL[0] = 1.f;
            RL[1] = __ldg(&rest[s - 1]);
            {
                float4 a = __ldg((const float4*)(rest + s));
                float4 b = __ldg((const float4*)(rest + s + 4));
                RL[2] = a.x; RL[3] = a.y; RL[4] = a.z; RL[5] = a.w;
                RL[6] = b.x; RL[7] = b.y; RL[8] = b.z; RL[9] = b.w;
            }
            RL[10] = 1.f;
        } else {
            {
                float px[PPT + 4], py[PPT + 4];
                #pragma unroll
                for (int j = 0; j < PPT + 4; j++) {
                    int g = max(0, min(s - 2 + j, N - 1));
                    float2 v = __ldg(&pos[g]);
                    px[j] = v.x; py[j] = v.y;
                }
                #pragma unroll
                for (int j = 0; j < NE; j++) {
                    Ex[j] = px[j + 1] - px[j];
                    Ey[j] = py[j + 1] - py[j];
                }
            }
            #pragma unroll
            for (int i = 0; i < NH; i++) {
                int h = s - 2 + i;
                bool v = (h >= 0) && (h < H);
                TH[i] = v ? __ldg(&th_ss[h]) : 0.f;
                int2 b = v ? __ldg(&buckle[h]) : make_int2(0, 0);
                B0[i] = (float)b.x; B1[i] = (float)b.y;
                if (!v) { Ex[i] = 0.f; }  // marker unused; validity re-derived below
            }
            #pragma unroll
            for (int j = 0; j < NE; j++) {
                int e = s - 2 + j;
                RL[j] = ((e >= 0) && (e <= H)) ? __ldg(&rest[e]) : 0.f; // 0 marks invalid
            }
        }

        #pragma unroll
        for (int j = 0; j < PPT; j++) { Gx[j] = 0.f; Gy[j] = 0.f; }

        // ---------------- hinges (10 independent chains) ----------------
        #pragma unroll
        for (int i = 0; i < NH; i++) {
            bool vh = fast || (((s - 2 + i) >= 0) && ((s - 2 + i) < H));
            float v1x = Ex[i],     v1y = Ey[i];
            float v2x = Ex[i + 1], v2y = Ey[i + 1];
            float cr = v1x * v2y - v1y * v2x;
            float dt = fmaf(v1x, v2x, v1y * v2y);
            cr = vh ? cr : 0.f;
            dt = vh ? dt : 1.f;
            float theta = fast_atan2f(cr, dt);

            float th = TH[i];
            bool m0 = fmaf(theta, B0[i], th) > 0.f;
            bool m1 = fmaf(theta, B1[i], th) > 0.f;
            float keff = (m0 ? k_stiff : k_soft) + (m1 ? k_stiff : k_soft);

            float diff = theta - th;
            float g = keff * diff;
            if (i >= 2) rot_e = fmaf(0.5f * g, diff, rot_e);

            float inv = __fdividef(g, fmaf(cr, cr, dt * dt));
            float d1x = ( dt * v2y - cr * v2x) * inv;
            float d1y = (-dt * v2x - cr * v2y) * inv;
            float d2x = (-dt * v1y - cr * v1x) * inv;
            float d2y = ( dt * v1x - cr * v1y) * inv;

            if (i >= 2) { Gx[i - 2] -= d1x;        Gy[i - 2] -= d1y; }
            if (i >= 1 && i - 1 < PPT) {
                Gx[i - 1] += d1x - d2x;  Gy[i - 1] += d1y - d2y;
            }
            if (i < PPT) { Gx[i] += d2x;  Gy[i] += d2y; }
        }

        // ------------- stretch fused into G (edges j = 1..9) -------------
        #pragma unroll
        for (int j = 1; j < NE - 1; j++) {
            bool ve = fast || (((s - 2 + j) >= 0) && ((s - 2 + j) <= H));
            float ex = Ex[j], ey = Ey[j];
            float lensq = fmaf(ex, ex, ey * ey);
            lensq = ve ? lensq : 1.f;
            float rsq = rsqrtf(lensq);
            float len = lensq * rsq;
            float dl  = ve ? (len - RL[j]) : 0.f;
            float c   = k_stretch * dl * rsq;
            float fx = c * ex, fy = c * ey;
            if (j >= 2) str_e = fmaf(0.5f * k_stretch * dl, dl, str_e);
            // edge vec j is edge (s-2+j): tail point local idx j-2, head idx j-1
            if (j >= 2)          { Gx[j - 2] -= fx; Gy[j - 2] -= fy; }
            if (j - 1 < PPT)     { Gx[j - 1] += fx; Gy[j - 1] += fy; }
        }

        // ---------------- force writes ----------------
        if (fast) {
            out[3 + 2 * s] = -Gx[0];
            float4* o4 = (float4*)(out + 4 + 2 * s);
            o4[0] = make_float4(-Gy[0], -Gx[1], -Gy[1], -Gx[2]);
            o4[1] = make_float4(-Gy[2], -Gx[3], -Gy[3], -Gx[4]);
            o4[2] = make_float4(-Gy[4], -Gx[5], -Gy[5], -Gx[6]);
            out[16 + 2 * s] = -Gy[6];
            out[17 + 2 * s] = -Gx[7];
            out[18 + 2 * s] = -Gy[7];
        } else {
            #pragma unroll
            for (int j = 0; j < PPT; j++) {
                int p = s + j;
                if (p < N) {
                    bool z = (p < 2);
                    out[3 + 2 * p]     = z ? 0.f : -Gx[j];
                    out[3 + 2 * p + 1] = z ? 0.f : -Gy[j];
                }
            }
        }
    }

    // ---------------- energy reduction ----------------
    float r = rot_e, sv = str_e;
    #pragma unroll
    for (int off = 16; off > 0; off >>= 1) {
        r  += __shfl_down_sync(0xffffffffu, r,  off);
        sv += __shfl_down_sync(0xffffffffu, sv, off);
    }
    const int lane = threadIdx.x & 31;
    const int wid  = threadIdx.x >> 5;
    if (lane == 0) {
        int slot = (blockIdx.x * (TPB / 32) + wid) & 63;
        atomicAdd(&g_rot_acc[slot], (double)r);
        atomicAdd(&g_str_acc[slot], (double)sv);
        __threadfence();
        unsigned tk = atomicAdd(&g_ticket, 1u);
        if (tk == totalWarps - 1u) {
            double R = 0.0, S = 0.0;
            #pragma unroll
            for (int i = 0; i < 64; i++) {
                R += g_rot_acc[i]; g_rot_acc[i] = 0.0;
                S += g_str_acc[i]; g_str_acc[i] = 0.0;
            }
            out[0] = (float)(R + S);
            out[1] = (float)R;
            out[2] = (float)S;
            g_ticket = 0u;
        }
    }
}

extern "C" void kernel_launch(void* const* d_in, const int* in_sizes, int n_in,
                              void* d_out, int out_size) {
    const float2* pos      = (const float2*)d_in[0];
    const float*  th_ss    = (const float*)d_in[1];
    const float*  rest     = (const float*)d_in[2];
    const float*  kstiff   = (const float*)d_in[3];
    const float*  ksoft    = (const float*)d_in[4];
    const float*  kstretch = (const float*)d_in[5];
    const int2*   buckle   = (const int2*)d_in[6];
    float* out = (float*)d_out;

    const int H = in_sizes[1];
    const int N = H + 2;
    const int threads_needed = (N + PPT - 1) / PPT;
    const int blocks = (threads_needed + TPB - 1) / TPB;
    const unsigned totalWarps = (unsigned)blocks * (TPB / 32);

    chain_kernel<<<blocks, TPB>>>(pos, th_ss, rest, kstiff, ksoft, kstretch,
                                  buckle, out, H, totalWarps);
}